// round 1
// baseline (speedup 1.0000x reference)
#include <cuda_runtime.h>

// Problem constants
#define B_     2048
#define DDATA  768
#define DD0    128     // d_dict0 == n_sae
#define NSAE   128
#define DD     32      // d_dict per expert
#define NFLAT  4096    // NSAE*DD
#define KCAT   4352    // NFLAT + 128 (acts0) + 128 (gate)

// Scratch: A1 = [B, KCAT] = (acts1 flat | acts0 | gate), plus fused encoder bias
__device__ float g_A1[B_ * KCAT];     // ~35.7 MB
__device__ float g_cb1[NFLAT];        // cb1[j,k] = b_enc1[j,k] - sum_d b_dec1[j,d]*W_enc1[j,d,k]

// ---------------------------------------------------------------------------
// cb1 precompute: 128 blocks (j) x 32 threads (k)
// ---------------------------------------------------------------------------
__global__ void k_build_cb1(const float* __restrict__ W_enc1,
                            const float* __restrict__ b_enc1,
                            const float* __restrict__ b_dec1) {
    int j = blockIdx.x;
    int k = threadIdx.x;
    float s = b_enc1[j * DD + k];
    const float* w  = W_enc1 + (size_t)j * DDATA * DD + k;
    const float* bd = b_dec1 + (size_t)j * DDATA;
    #pragma unroll 4
    for (int d = 0; d < DDATA; ++d)
        s -= bd[d] * w[d * DD];
    g_cb1[j * DD + k] = s;
}

// ---------------------------------------------------------------------------
// acts0 + gate: writes into g_A1 columns [4096,4224) = acts0, [4224,4352) = gate
// 8 batch rows per block, 128 threads (one per dict0 unit)
// ---------------------------------------------------------------------------
__global__ void k_acts0(const float* __restrict__ x,
                        const float* __restrict__ W_enc0,
                        const float* __restrict__ b_enc0,
                        const float* __restrict__ b_dec0) {
    __shared__ float xs[8 * DDATA];   // 24 KB
    const int b0 = blockIdx.x * 8;
    const int j  = threadIdx.x;       // 0..127

    for (int idx = threadIdx.x; idx < 8 * DDATA; idx += 128)
        xs[idx] = x[(size_t)b0 * DDATA + idx] - b_dec0[idx % DDATA];
    __syncthreads();

    float acc[8];
    #pragma unroll
    for (int r = 0; r < 8; ++r) acc[r] = 0.f;

    for (int d = 0; d < DDATA; ++d) {
        float w = W_enc0[d * DD0 + j];
        #pragma unroll
        for (int r = 0; r < 8; ++r) acc[r] += xs[r * DDATA + d] * w;
    }

    float be = b_enc0[j];
    #pragma unroll
    for (int r = 0; r < 8; ++r) {
        float v = acc[r] + be;
        float a = v > 0.f ? v : 0.f;
        float g = v > 0.f ? 1.f : 0.f;
        g_A1[(size_t)(b0 + r) * KCAT + NFLAT + j]       = a;
        g_A1[(size_t)(b0 + r) * KCAT + NFLAT + 128 + j] = g;
    }
}

// ---------------------------------------------------------------------------
// GEMM1: pre[b, n] = sum_d x[b,d] * W_enc1[n>>5, d, n&31], n in [0,4096)
// epilogue: acts1 = relu(pre + cb1[n]) * gate[b, n>>5]  -> g_A1[b, n]
// 64x64 block tile, 256 threads, 4x4 microtile, K-chunk 16
// ---------------------------------------------------------------------------
__global__ void k_gemm1(const float* __restrict__ x,
                        const float* __restrict__ W_enc1) {
    __shared__ float As[16][64];
    __shared__ float Bs[16][64];

    const int tid = threadIdx.x;
    const int m0  = blockIdx.y * 64;
    const int n0  = blockIdx.x * 64;
    const int tx  = tid & 15;     // 0..15 -> n
    const int ty  = tid >> 4;     // 0..15 -> m

    // A-load mapping: 64 rows x 16 cols, float4 per thread
    const int arow = tid >> 2;            // 0..63
    const int acol = (tid & 3) * 4;       // 0,4,8,12
    // B-load mapping: 16 rows x 64 cols, float4 per thread
    const int brow = tid >> 4;            // 0..15
    const int bcol = (tid & 15) * 4;      // 0..60

    const int nB = n0 + bcol;
    const int jB = nB >> 5;
    const int kB = nB & 31;

    float acc[4][4];
    #pragma unroll
    for (int i = 0; i < 4; ++i)
        #pragma unroll
        for (int jj = 0; jj < 4; ++jj) acc[i][jj] = 0.f;

    for (int kt = 0; kt < DDATA; kt += 16) {
        float4 av = *(const float4*)&x[(size_t)(m0 + arow) * DDATA + kt + acol];
        As[acol + 0][arow] = av.x;
        As[acol + 1][arow] = av.y;
        As[acol + 2][arow] = av.z;
        As[acol + 3][arow] = av.w;

        float4 bv = *(const float4*)&W_enc1[((size_t)jB * DDATA + kt + brow) * DD + kB];
        *(float4*)&Bs[brow][bcol] = bv;
        __syncthreads();

        #pragma unroll
        for (int kk = 0; kk < 16; ++kk) {
            float4 a4 = *(const float4*)&As[kk][ty * 4];
            float4 b4 = *(const float4*)&Bs[kk][tx * 4];
            float ar[4] = {a4.x, a4.y, a4.z, a4.w};
            float br[4] = {b4.x, b4.y, b4.z, b4.w};
            #pragma unroll
            for (int i = 0; i < 4; ++i)
                #pragma unroll
                for (int jj = 0; jj < 4; ++jj)
                    acc[i][jj] += ar[i] * br[jj];
        }
        __syncthreads();
    }

    // epilogue
    #pragma unroll
    for (int i = 0; i < 4; ++i) {
        int m = m0 + ty * 4 + i;
        #pragma unroll
        for (int jj = 0; jj < 4; ++jj) {
            int n = n0 + tx * 4 + jj;
            float v = acc[i][jj] + g_cb1[n];
            float gate = g_A1[(size_t)m * KCAT + NFLAT + 128 + (n >> 5)];
            float r = (v > 0.f ? v : 0.f) * gate;
            g_A1[(size_t)m * KCAT + n] = r;
        }
    }
}

// ---------------------------------------------------------------------------
// GEMM2: out[b, c] = sum_{k<4352} A1[b,k] * Bcat[k,c] + b_dec0[c]
// Bcat rows: [0,4096) = W_dec1 flat, [4096,4224) = W_dec0, [4224,4352) = b_dec1.
// Region boundaries are multiples of 16 so each k-tile row is region-uniform.
// ---------------------------------------------------------------------------
__global__ void k_gemm2(const float* __restrict__ W_dec1,
                        const float* __restrict__ W_dec0,
                        const float* __restrict__ b_dec1,
                        const float* __restrict__ b_dec0,
                        float* __restrict__ out) {
    __shared__ float As[16][64];
    __shared__ float Bs[16][64];

    const int tid = threadIdx.x;
    const int m0  = blockIdx.y * 64;
    const int n0  = blockIdx.x * 64;
    const int tx  = tid & 15;
    const int ty  = tid >> 4;

    const int arow = tid >> 2;
    const int acol = (tid & 3) * 4;
    const int brow = tid >> 4;
    const int bcol = (tid & 15) * 4;

    float acc[4][4];
    #pragma unroll
    for (int i = 0; i < 4; ++i)
        #pragma unroll
        for (int jj = 0; jj < 4; ++jj) acc[i][jj] = 0.f;

    for (int kt = 0; kt < KCAT; kt += 16) {
        float4 av = *(const float4*)&g_A1[(size_t)(m0 + arow) * KCAT + kt + acol];
        As[acol + 0][arow] = av.x;
        As[acol + 1][arow] = av.y;
        As[acol + 2][arow] = av.z;
        As[acol + 3][arow] = av.w;

        int krow = kt + brow;
        const float* bsrc;
        if (krow < NFLAT)            bsrc = W_dec1 + (size_t)krow * DDATA;
        else if (krow < NFLAT + 128) bsrc = W_dec0 + (size_t)(krow - NFLAT) * DDATA;
        else                         bsrc = b_dec1 + (size_t)(krow - NFLAT - 128) * DDATA;
        float4 bv = *(const float4*)&bsrc[n0 + bcol];
        *(float4*)&Bs[brow][bcol] = bv;
        __syncthreads();

        #pragma unroll
        for (int kk = 0; kk < 16; ++kk) {
            float4 a4 = *(const float4*)&As[kk][ty * 4];
            float4 b4 = *(const float4*)&Bs[kk][tx * 4];
            float ar[4] = {a4.x, a4.y, a4.z, a4.w};
            float br[4] = {b4.x, b4.y, b4.z, b4.w};
            #pragma unroll
            for (int i = 0; i < 4; ++i)
                #pragma unroll
                for (int jj = 0; jj < 4; ++jj)
                    acc[i][jj] += ar[i] * br[jj];
        }
        __syncthreads();
    }

    #pragma unroll
    for (int i = 0; i < 4; ++i) {
        int m = m0 + ty * 4 + i;
        #pragma unroll
        for (int jj = 0; jj < 4; ++jj) {
            int n = n0 + tx * 4 + jj;
            out[(size_t)m * DDATA + n] = acc[i][jj] + b_dec0[n];
        }
    }
}

// ---------------------------------------------------------------------------
extern "C" void kernel_launch(void* const* d_in, const int* in_sizes, int n_in,
                              void* d_out, int out_size) {
    const float* x      = (const float*)d_in[0];
    const float* W_enc0 = (const float*)d_in[1];
    const float* b_enc0 = (const float*)d_in[2];
    const float* W_dec0 = (const float*)d_in[3];
    const float* b_dec0 = (const float*)d_in[4];
    const float* W_enc1 = (const float*)d_in[5];
    const float* b_enc1 = (const float*)d_in[6];
    const float* W_dec1 = (const float*)d_in[7];
    const float* b_dec1 = (const float*)d_in[8];
    float* out = (float*)d_out;

    k_build_cb1<<<NSAE, DD>>>(W_enc1, b_enc1, b_dec1);
    k_acts0<<<B_ / 8, 128>>>(x, W_enc0, b_enc0, b_dec0);
    k_gemm1<<<dim3(NFLAT / 64, B_ / 64), 256>>>(x, W_enc1);
    k_gemm2<<<dim3(DDATA / 64, B_ / 64), 256>>>(W_dec1, W_dec0, b_dec1, b_dec0, out);
}

// round 3
// speedup vs baseline: 1.3655x; 1.3655x over previous
#include <cuda_runtime.h>

// Problem constants
#define B_     2048
#define DDATA  768
#define DD0    128
#define NSAE   128
#define DD     32
#define NFLAT  4096
#define KCAT   4352   // NFLAT + 128 (acts0) + 128 (gate)

// GEMM tiling
#define BM 128
#define BN 64
#define KC 16
#define ASTR 20   // As row stride (floats): conflict-free fragment LDS
#define BSTR 68   // Bs row stride (floats): conflict-free fragment LDS

__device__ float g_A1[B_ * KCAT];   // (acts1 | acts0 | gate)
__device__ float g_cb1[NFLAT];      // fused encoder bias per flat unit

// ---------------------------------------------------------------------------
__device__ __forceinline__ unsigned f2tf(float f) {
    unsigned u; asm("cvt.rna.tf32.f32 %0, %1;" : "=r"(u) : "f"(f)); return u;
}
__device__ __forceinline__ void cp16(void* smem, const void* g) {
    unsigned s = (unsigned)__cvta_generic_to_shared(smem);
    asm volatile("cp.async.cg.shared.global [%0], [%1], 16;\n" :: "r"(s), "l"(g));
}
__device__ __forceinline__ void cp_commit() { asm volatile("cp.async.commit_group;\n"); }
template<int N> __device__ __forceinline__ void cp_wait() {
    asm volatile("cp.async.wait_group %0;\n" :: "n"(N));
}
__device__ __forceinline__ void mma_tf32(float* d, const unsigned* a, const unsigned* b) {
    asm volatile(
        "mma.sync.aligned.m16n8k8.row.col.f32.tf32.tf32.f32 "
        "{%0,%1,%2,%3}, {%4,%5,%6,%7}, {%8,%9}, {%0,%1,%2,%3};\n"
        : "+f"(d[0]), "+f"(d[1]), "+f"(d[2]), "+f"(d[3])
        : "r"(a[0]), "r"(a[1]), "r"(a[2]), "r"(a[3]), "r"(b[0]), "r"(b[1]));
}

// ---------------------------------------------------------------------------
// cb1[j,k] = b_enc1[j,k] - sum_d b_dec1[j,d] * W_enc1[j,d,k]
// ---------------------------------------------------------------------------
__global__ void k_build_cb1(const float* __restrict__ W_enc1,
                            const float* __restrict__ b_enc1,
                            const float* __restrict__ b_dec1) {
    int j = blockIdx.x;
    int k = threadIdx.x;
    float s = b_enc1[j * DD + k];
    const float* w  = W_enc1 + (size_t)j * DDATA * DD + k;
    const float* bd = b_dec1 + (size_t)j * DDATA;
    #pragma unroll 4
    for (int d = 0; d < DDATA; ++d)
        s -= bd[d] * w[d * DD];
    g_cb1[j * DD + k] = s;
}

// ---------------------------------------------------------------------------
// acts0 + gate into g_A1 cols [4096,4224)=acts0, [4224,4352)=gate (fp32 exact)
// ---------------------------------------------------------------------------
__global__ void k_acts0(const float* __restrict__ x,
                        const float* __restrict__ W_enc0,
                        const float* __restrict__ b_enc0,
                        const float* __restrict__ b_dec0) {
    __shared__ float xs[8 * DDATA];
    const int b0 = blockIdx.x * 8;
    const int j  = threadIdx.x;

    for (int idx = threadIdx.x; idx < 8 * DDATA; idx += 128)
        xs[idx] = x[(size_t)b0 * DDATA + idx] - b_dec0[idx % DDATA];
    __syncthreads();

    float acc[8];
    #pragma unroll
    for (int r = 0; r < 8; ++r) acc[r] = 0.f;

    for (int d = 0; d < DDATA; ++d) {
        float w = W_enc0[d * DD0 + j];
        #pragma unroll
        for (int r = 0; r < 8; ++r) acc[r] += xs[r * DDATA + d] * w;
    }

    float be = b_enc0[j];
    #pragma unroll
    for (int r = 0; r < 8; ++r) {
        float v = acc[r] + be;
        g_A1[(size_t)(b0 + r) * KCAT + NFLAT + j]       = v > 0.f ? v : 0.f;
        g_A1[(size_t)(b0 + r) * KCAT + NFLAT + 128 + j] = v > 0.f ? 1.f : 0.f;
    }
}

// ---------------------------------------------------------------------------
// GEMM1 (tf32 mma): pre[b,n] = sum_d x[b,d] * W_enc1[n>>5, d, n&31]
// epilogue: g_A1[b,n] = relu(pre + cb1[n]) * gate[b, n>>5]
// ---------------------------------------------------------------------------
__global__ __launch_bounds__(256, 2)
void k_gemm1(const float* __restrict__ x, const float* __restrict__ W_enc1) {
    __shared__ float As[2][BM][ASTR];
    __shared__ float Bs[2][KC][BSTR];

    const int tid  = threadIdx.x;
    const int lane = tid & 31, wid = tid >> 5;
    const int wm0  = (wid & 3) * 32, wn0 = (wid >> 2) * 32;
    const int lr   = lane >> 2, lc = lane & 3;
    const int m0   = blockIdx.y * BM, n0 = blockIdx.x * BN;

    const int arow = tid >> 1, acol = (tid & 1) * 8;   // A: 128 rows x 16 k
    const int brow = tid >> 4, bcol = (tid & 15) * 4;  // B: 16 k x 64 n
    const int nB = n0 + bcol, jB = nB >> 5, kB = nB & 31;

    float acc[2][4][4];
    #pragma unroll
    for (int mt = 0; mt < 2; ++mt)
        #pragma unroll
        for (int nt = 0; nt < 4; ++nt)
            #pragma unroll
            for (int c = 0; c < 4; ++c) acc[mt][nt][c] = 0.f;

    const float* aSrc = x + (size_t)(m0 + arow) * DDATA + acol;

    // prologue: chunk 0
    {
        cp16(&As[0][arow][acol],     aSrc);
        cp16(&As[0][arow][acol + 4], aSrc + 4);
        cp16(&Bs[0][brow][bcol], W_enc1 + ((size_t)jB * DDATA + brow) * DD + kB);
        cp_commit();
    }

    const int T = DDATA / KC;  // 48
    for (int t = 0; t < T; ++t) {
        const int buf = t & 1;
        if (t + 1 < T) {
            const int kt = (t + 1) * KC;
            cp16(&As[buf ^ 1][arow][acol],     aSrc + kt);
            cp16(&As[buf ^ 1][arow][acol + 4], aSrc + kt + 4);
            cp16(&Bs[buf ^ 1][brow][bcol],
                 W_enc1 + ((size_t)jB * DDATA + kt + brow) * DD + kB);
            cp_commit();
            cp_wait<1>();
        } else {
            cp_wait<0>();
        }
        __syncthreads();

        #pragma unroll
        for (int ks = 0; ks < 2; ++ks) {
            const int kb = ks * 8;
            unsigned a[2][4], b[4][2];
            #pragma unroll
            for (int mt = 0; mt < 2; ++mt) {
                const int r = wm0 + mt * 16 + lr;
                a[mt][0] = f2tf(As[buf][r][kb + lc]);
                a[mt][1] = f2tf(As[buf][r + 8][kb + lc]);
                a[mt][2] = f2tf(As[buf][r][kb + lc + 4]);
                a[mt][3] = f2tf(As[buf][r + 8][kb + lc + 4]);
            }
            #pragma unroll
            for (int nt = 0; nt < 4; ++nt) {
                const int c = wn0 + nt * 8 + lr;
                b[nt][0] = f2tf(Bs[buf][kb + lc][c]);
                b[nt][1] = f2tf(Bs[buf][kb + lc + 4][c]);
            }
            #pragma unroll
            for (int mt = 0; mt < 2; ++mt)
                #pragma unroll
                for (int nt = 0; nt < 4; ++nt)
                    mma_tf32(acc[mt][nt], a[mt], b[nt]);
        }
        __syncthreads();
    }

    // epilogue: relu(+cb1) * gate -> g_A1
    const int jexp = (n0 + wn0) >> 5;   // warp N-tile sits inside one expert
    #pragma unroll
    for (int mt = 0; mt < 2; ++mt) {
        const int r0 = m0 + wm0 + mt * 16 + lr;
        const float g0 = g_A1[(size_t)r0 * KCAT + NFLAT + 128 + jexp];
        const float g1 = g_A1[(size_t)(r0 + 8) * KCAT + NFLAT + 128 + jexp];
        #pragma unroll
        for (int nt = 0; nt < 4; ++nt) {
            const int n = n0 + wn0 + nt * 8 + 2 * lc;
            const float c0 = g_cb1[n], c1 = g_cb1[n + 1];
            float2 o0 = make_float2(fmaxf(acc[mt][nt][0] + c0, 0.f) * g0,
                                    fmaxf(acc[mt][nt][1] + c1, 0.f) * g0);
            float2 o1 = make_float2(fmaxf(acc[mt][nt][2] + c0, 0.f) * g1,
                                    fmaxf(acc[mt][nt][3] + c1, 0.f) * g1);
            *(float2*)&g_A1[(size_t)r0 * KCAT + n]       = o0;
            *(float2*)&g_A1[(size_t)(r0 + 8) * KCAT + n] = o1;
        }
    }
}

// ---------------------------------------------------------------------------
// GEMM2 (tf32 mma): out[b,c] = sum_k A1[b,k]*Bcat[k,c] + b_dec0[c]
// Bcat rows: [0,4096)=W_dec1 flat, [4096,4224)=W_dec0, [4224,4352)=b_dec1
// ---------------------------------------------------------------------------
__global__ __launch_bounds__(256, 2)
void k_gemm2(const float* __restrict__ W_dec1,
             const float* __restrict__ W_dec0,
             const float* __restrict__ b_dec1,
             const float* __restrict__ b_dec0,
             float* __restrict__ out) {
    __shared__ float As[2][BM][ASTR];
    __shared__ float Bs[2][KC][BSTR];

    const int tid  = threadIdx.x;
    const int lane = tid & 31, wid = tid >> 5;
    const int wm0  = (wid & 3) * 32, wn0 = (wid >> 2) * 32;
    const int lr   = lane >> 2, lc = lane & 3;
    const int m0   = blockIdx.y * BM, n0 = blockIdx.x * BN;

    const int arow = tid >> 1, acol = (tid & 1) * 8;
    const int brow = tid >> 4, bcol = (tid & 15) * 4;

    float acc[2][4][4];
    #pragma unroll
    for (int mt = 0; mt < 2; ++mt)
        #pragma unroll
        for (int nt = 0; nt < 4; ++nt)
            #pragma unroll
            for (int c = 0; c < 4; ++c) acc[mt][nt][c] = 0.f;

    const float* aSrc = g_A1 + (size_t)(m0 + arow) * KCAT + acol;

    auto bRow = [&](int krow) -> const float* {
        if (krow < NFLAT)            return W_dec1 + (size_t)krow * DDATA;
        else if (krow < NFLAT + 128) return W_dec0 + (size_t)(krow - NFLAT) * DDATA;
        else                         return b_dec1 + (size_t)(krow - NFLAT - 128) * DDATA;
    };

    {
        cp16(&As[0][arow][acol],     aSrc);
        cp16(&As[0][arow][acol + 4], aSrc + 4);
        cp16(&Bs[0][brow][bcol], bRow(brow) + n0 + bcol);
        cp_commit();
    }

    const int T = KCAT / KC;  // 272
    for (int t = 0; t < T; ++t) {
        const int buf = t & 1;
        if (t + 1 < T) {
            const int kt = (t + 1) * KC;
            cp16(&As[buf ^ 1][arow][acol],     aSrc + kt);
            cp16(&As[buf ^ 1][arow][acol + 4], aSrc + kt + 4);
            cp16(&Bs[buf ^ 1][brow][bcol], bRow(kt + brow) + n0 + bcol);
            cp_commit();
            cp_wait<1>();
        } else {
            cp_wait<0>();
        }
        __syncthreads();

        #pragma unroll
        for (int ks = 0; ks < 2; ++ks) {
            const int kb = ks * 8;
            unsigned a[2][4], b[4][2];
            #pragma unroll
            for (int mt = 0; mt < 2; ++mt) {
                const int r = wm0 + mt * 16 + lr;
                a[mt][0] = f2tf(As[buf][r][kb + lc]);
                a[mt][1] = f2tf(As[buf][r + 8][kb + lc]);
                a[mt][2] = f2tf(As[buf][r][kb + lc + 4]);
                a[mt][3] = f2tf(As[buf][r + 8][kb + lc + 4]);
            }
            #pragma unroll
            for (int nt = 0; nt < 4; ++nt) {
                const int c = wn0 + nt * 8 + lr;
                b[nt][0] = f2tf(Bs[buf][kb + lc][c]);
                b[nt][1] = f2tf(Bs[buf][kb + lc + 4][c]);
            }
            #pragma unroll
            for (int mt = 0; mt < 2; ++mt)
                #pragma unroll
                for (int nt = 0; nt < 4; ++nt)
                    mma_tf32(acc[mt][nt], a[mt], b[nt]);
        }
        __syncthreads();
    }

    #pragma unroll
    for (int mt = 0; mt < 2; ++mt) {
        const int r0 = m0 + wm0 + mt * 16 + lr;
        #pragma unroll
        for (int nt = 0; nt < 4; ++nt) {
            const int n = n0 + wn0 + nt * 8 + 2 * lc;
            const float c0 = b_dec0[n], c1 = b_dec0[n + 1];
            float2 o0 = make_float2(acc[mt][nt][0] + c0, acc[mt][nt][1] + c1);
            float2 o1 = make_float2(acc[mt][nt][2] + c0, acc[mt][nt][3] + c1);
            *(float2*)&out[(size_t)r0 * DDATA + n]       = o0;
            *(float2*)&out[(size_t)(r0 + 8) * DDATA + n] = o1;
        }
    }
}

// ---------------------------------------------------------------------------
extern "C" void kernel_launch(void* const* d_in, const int* in_sizes, int n_in,
                              void* d_out, int out_size) {
    const float* x      = (const float*)d_in[0];
    const float* W_enc0 = (const float*)d_in[1];
    const float* b_enc0 = (const float*)d_in[2];
    const float* W_dec0 = (const float*)d_in[3];
    const float* b_dec0 = (const float*)d_in[4];
    const float* W_enc1 = (const float*)d_in[5];
    const float* b_enc1 = (const float*)d_in[6];
    const float* W_dec1 = (const float*)d_in[7];
    const float* b_dec1 = (const float*)d_in[8];
    float* out = (float*)d_out;

    k_build_cb1<<<NSAE, DD>>>(W_enc1, b_enc1, b_dec1);
    k_acts0<<<B_ / 8, 128>>>(x, W_enc0, b_enc0, b_dec0);
    k_gemm1<<<dim3(NFLAT / BN, B_ / BM), 256>>>(x, W_enc1);
    k_gemm2<<<dim3(DDATA / BN, B_ / BM), 256>>>(W_dec1, W_dec0, b_dec1, b_dec0, out);
}

// round 11
// speedup vs baseline: 2.4853x; 1.8201x over previous
#include <cuda_runtime.h>
#include <cstdint>

// Problem constants
#define B_     2048
#define DDATA  768
#define DD0    128
#define NSAE   128
#define DD     32
#define NFLAT  4096
#define KCAT   4352   // NFLAT + 128 (acts0) + 128 (gate)

// Scratch. All k-dimensions stored with within-8-group column order
// [0,4,1,5,2,6,3,7] so mma fragment register pairs (k, k+4) are adjacent.
// NOTE: these are referenced ONLY from device code (host-side symbol decay
// gives garbage pointers — that was the R5/R8/R9 bug).
__device__ float g_A1 [B_ * KCAT];      // (acts1 | acts0 | gate), k-permuted cols
__device__ float g_cb1[NFLAT];          // fused encoder bias, LOGICAL index
__device__ float g_xr [B_ * DDATA];     // x, tf32-rounded, d-permuted
__device__ float g_B1T[NFLAT * DDATA];  // [n][d] = W_enc1[n>>5][d][n&31], d-permuted
__device__ float g_B2T[DDATA * KCAT];   // [c][k] = Bcat[k][c], k-permuted

// ---------------------------------------------------------------------------
__device__ __forceinline__ int pos8(int u) {          // u in 0..7
    return (u < 4) ? (2 * u) : (2 * (u - 4) + 1);
}
__device__ __forceinline__ int g8pos(int u) {         // permute within 8-groups
    return (u & ~7) | pos8(u & 7);
}
__device__ __forceinline__ unsigned f2tf(float f) {
    unsigned u; asm("cvt.rna.tf32.f32 %0, %1;" : "=r"(u) : "f"(f)); return u;
}
__device__ __forceinline__ float tfr(float f) { return __uint_as_float(f2tf(f)); }

__device__ __forceinline__ void cp16(void* smemp, const void* g) {
    unsigned s = (unsigned)__cvta_generic_to_shared(smemp);
    asm volatile("cp.async.cg.shared.global [%0], [%1], 16;\n" :: "r"(s), "l"(g));
}
__device__ __forceinline__ void cp_commit() { asm volatile("cp.async.commit_group;\n"); }
template<int N> __device__ __forceinline__ void cp_wait() {
    asm volatile("cp.async.wait_group %0;\n" :: "n"(N));
}
__device__ __forceinline__ void mma_tf32(float* d, const uint32_t* a, const uint32_t* b) {
    asm volatile(
        "mma.sync.aligned.m16n8k8.row.col.f32.tf32.tf32.f32 "
        "{%0,%1,%2,%3}, {%4,%5,%6,%7}, {%8,%9}, {%0,%1,%2,%3};\n"
        : "+f"(d[0]), "+f"(d[1]), "+f"(d[2]), "+f"(d[3])
        : "r"(a[0]), "r"(a[1]), "r"(a[2]), "r"(a[3]), "r"(b[0]), "r"(b[1]));
}

// ---------------------------------------------------------------------------
// Prep kernels (reference scratch globals directly in device code)
// ---------------------------------------------------------------------------
// g_xr[b][perm(d)] = round(x[b][d])
__global__ void k_round_x(const float* __restrict__ x) {
    int i = blockIdx.x * blockDim.x + threadIdx.x;    // over B_*DDATA
    int row = i / DDATA, col = i % DDATA;
    g_xr[(size_t)row * DDATA + g8pos(col)] = tfr(x[i]);
}

// g_B1T[j*32+k][perm(d)] = round(W_enc1[j][d][k])
__global__ void k_t1(const float* __restrict__ W_enc1) {
    __shared__ float ts[32][33];
    const int j = blockIdx.x, d0 = blockIdx.y * 32;
    const int tx = threadIdx.x, ty = threadIdx.y;
    #pragma unroll
    for (int r = 0; r < 4; ++r) {
        int d = ty + 8 * r;
        ts[d][tx] = W_enc1[((size_t)j * DDATA + d0 + d) * DD + tx];
    }
    __syncthreads();
    #pragma unroll
    for (int r = 0; r < 4; ++r) {
        int k = ty + 8 * r;
        g_B1T[(size_t)(j * 32 + k) * DDATA + d0 + g8pos(tx)] = tfr(ts[tx][k]);
    }
}

// g_B2T[c][perm(kk)] = round(Bcat[kk][c]); Bcat = W_dec1 flat | W_dec0 | b_dec1
__global__ void k_t2(const float* __restrict__ W_dec1,
                     const float* __restrict__ W_dec0,
                     const float* __restrict__ b_dec1) {
    __shared__ float ts[32][33];
    const int kk0 = blockIdx.x * 32, c0 = blockIdx.y * 32;
    const int tx = threadIdx.x, ty = threadIdx.y;
    #pragma unroll
    for (int r = 0; r < 4; ++r) {
        int kr = kk0 + ty + 8 * r;
        const float* row = (kr < NFLAT) ? W_dec1 + (size_t)kr * DDATA
                         : (kr < NFLAT + 128) ? W_dec0 + (size_t)(kr - NFLAT) * DDATA
                         : b_dec1 + (size_t)(kr - NFLAT - 128) * DDATA;
        ts[ty + 8 * r][tx] = row[c0 + tx];
    }
    __syncthreads();
    #pragma unroll
    for (int r = 0; r < 4; ++r) {
        int c = ty + 8 * r;
        g_B2T[(size_t)(c0 + c) * KCAT + kk0 + g8pos(tx)] = tfr(ts[tx][c]);
    }
}

// cb1[j,k] = b_enc1[j,k] - sum_d b_dec1[j,d]*W_enc1[j,d,k]  (exact fp32, LOGICAL)
__global__ void k_cb1(const float* __restrict__ W_enc1,
                      const float* __restrict__ b_enc1,
                      const float* __restrict__ b_dec1) {
    __shared__ float red[8][32];
    const int j = blockIdx.x;
    const int k = threadIdx.x & 31, s = threadIdx.x >> 5;
    float acc = 0.f;
    for (int d = s; d < DDATA; d += 8)
        acc += b_dec1[(size_t)j * DDATA + d] * W_enc1[((size_t)j * DDATA + d) * DD + k];
    red[s][k] = acc;
    __syncthreads();
    if (s == 0) {
        float t = 0.f;
        #pragma unroll
        for (int i = 0; i < 8; ++i) t += red[i][k];
        g_cb1[j * DD + k] = b_enc1[j * DD + k] - t;
    }
}

// acts0 + gate, exact fp32 compute (gates must not be tf32-decided).
// Stored at permuted columns NFLAT + g8pos(j) and NFLAT + 128 + g8pos(j).
__global__ void k_acts0(const float* __restrict__ x,
                        const float* __restrict__ W_enc0,
                        const float* __restrict__ b_enc0,
                        const float* __restrict__ b_dec0) {
    __shared__ float xs[8 * DDATA];
    const int b0 = blockIdx.x * 8;
    const int j  = threadIdx.x;

    for (int idx = threadIdx.x; idx < 8 * DDATA; idx += 128)
        xs[idx] = x[(size_t)b0 * DDATA + idx] - b_dec0[idx % DDATA];
    __syncthreads();

    float acc[8];
    #pragma unroll
    for (int r = 0; r < 8; ++r) acc[r] = 0.f;
    for (int d = 0; d < DDATA; ++d) {
        float w = W_enc0[d * DD0 + j];
        #pragma unroll
        for (int r = 0; r < 8; ++r) acc[r] += xs[r * DDATA + d] * w;
    }
    float be = b_enc0[j];
    const int jp = g8pos(j);
    #pragma unroll
    for (int r = 0; r < 8; ++r) {
        float v = acc[r] + be;
        g_A1[(size_t)(b0 + r) * KCAT + NFLAT + jp]       = v > 0.f ? tfr(v) : 0.f;
        g_A1[(size_t)(b0 + r) * KCAT + NFLAT + 128 + jp] = v > 0.f ? 1.f : 0.f;
    }
}

// ---------------------------------------------------------------------------
// tf32 mma.sync GEMM, k-paired LDS.64 fragment loads, STATIC smem (<48KB).
// Operand/output buffers selected from DEVICE-SCOPE globals (not kernel args):
//   EPI1 (GEMM1, BN=64):  A=g_xr,  Bt=g_B1T, bias=g_cb1, Out=g_A1 (stride KCAT)
//   else (GEMM2, BN=96):  A=g_A1,  Bt=g_B2T, bias=arg,   Out=arg (stride DDATA)
// 8 warps as 4(M) x 2(N); warp tile 32 x BN/2; KC=16 double-buffered cp.async.
// ---------------------------------------------------------------------------
template<int BN, int KTOT, bool EPI1>
__global__ __launch_bounds__(256, 2)
void k_mma_gemm(const float* __restrict__ biasArg, float* __restrict__ OutArg) {
    constexpr int BM = 128, PAD = 24, KC = 16;
    constexpr int NT = BN / 16;                 // 8-wide n-frags per warp tile
    constexpr int T = KTOT / KC;

    const float* __restrict__ A  = EPI1 ? g_xr  : g_A1;
    const float* __restrict__ Bt = EPI1 ? g_B1T : g_B2T;

    __shared__ float Asm[2][BM][PAD];           // 24576 B
    __shared__ float Bsm[2][BN][PAD];           // BN=96: 18432 B (total 43008)

    const int tid = threadIdx.x, lane = tid & 31, wid = tid >> 5;
    const int wm0 = (wid & 3) * 32, wn0 = (wid >> 2) * (BN / 2);
    const int m0 = blockIdx.y * BM, n0 = blockIdx.x * BN;
    const int lr = lane >> 2, lc = lane & 3;

    auto loadChunk = [&](int st, int kt) {
        #pragma unroll
        for (int r = 0; r < 2; ++r) {
            int u = tid + 256 * r;               // 0..511: 128 rows x 4 cp16
            int row = u >> 2, c = u & 3;
            cp16(&Asm[st][row][c * 4],
                 A + (size_t)(m0 + row) * KTOT + kt + c * 4);
        }
        #pragma unroll
        for (int u = tid; u < BN * 4; u += 256) {
            int row = u >> 2, c = u & 3;
            cp16(&Bsm[st][row][c * 4],
                 Bt + (size_t)(n0 + row) * KTOT + kt + c * 4);
        }
        cp_commit();
    };

    float acc[2][NT][4] = {};

    loadChunk(0, 0);

    for (int t = 0; t < T; ++t) {
        const int st = t & 1;
        if (t + 1 < T) { loadChunk(st ^ 1, (t + 1) * KC); cp_wait<1>(); }
        else           { cp_wait<0>(); }
        __syncthreads();

        #pragma unroll
        for (int ks = 0; ks < 2; ++ks) {
            const int kb = ks * 8 + 2 * lc;      // stored pair = logical (lc, lc+4)
            uint32_t a[2][4];
            #pragma unroll
            for (int mt = 0; mt < 2; ++mt) {
                float2 lo = *(const float2*)&Asm[st][wm0 + mt * 16 + lr][kb];
                float2 hi = *(const float2*)&Asm[st][wm0 + mt * 16 + 8 + lr][kb];
                a[mt][0] = __float_as_uint(lo.x);   // a0: k=lc,   row m
                a[mt][1] = __float_as_uint(hi.x);   // a1: k=lc,   row m+8
                a[mt][2] = __float_as_uint(lo.y);   // a2: k=lc+4, row m
                a[mt][3] = __float_as_uint(hi.y);   // a3: k=lc+4, row m+8
            }
            #pragma unroll
            for (int nt = 0; nt < NT; ++nt) {
                float2 bv = *(const float2*)&Bsm[st][wn0 + nt * 8 + lr][kb];
                uint32_t b[2] = { __float_as_uint(bv.x), __float_as_uint(bv.y) };
                mma_tf32(acc[0][nt], a[0], b);
                mma_tf32(acc[1][nt], a[1], b);
            }
        }
        __syncthreads();
    }

    // Epilogue. D fragment cols (logical): u0 = 2*lc, u1 = 2*lc + 1 within 8-tile.
    const int u0 = 2 * lc, u1 = 2 * lc + 1;
    #pragma unroll
    for (int mt = 0; mt < 2; ++mt) {
        const int r0 = m0 + wm0 + mt * 16 + lr;
        if (EPI1) {
            const int j0 = (n0 + wn0) >> 5;     // warp n-tile = exactly 1 expert
            const float g0 = g_A1[(size_t)r0 * KCAT + NFLAT + 128 + g8pos(j0)];
            const float g1 = g_A1[(size_t)(r0 + 8) * KCAT + NFLAT + 128 + g8pos(j0)];
            #pragma unroll
            for (int nt = 0; nt < NT; ++nt) {
                const int nb = n0 + wn0 + nt * 8;       // logical tile base
                const float c0 = g_cb1[nb + u0], c1 = g_cb1[nb + u1];
                const int s0 = nb + pos8(u0), s1 = nb + pos8(u1);  // stored cols
                g_A1[(size_t)r0 * KCAT + s0] =
                    tfr(fmaxf(acc[mt][nt][0] + c0, 0.f) * g0);
                g_A1[(size_t)r0 * KCAT + s1] =
                    tfr(fmaxf(acc[mt][nt][1] + c1, 0.f) * g0);
                g_A1[(size_t)(r0 + 8) * KCAT + s0] =
                    tfr(fmaxf(acc[mt][nt][2] + c0, 0.f) * g1);
                g_A1[(size_t)(r0 + 8) * KCAT + s1] =
                    tfr(fmaxf(acc[mt][nt][3] + c1, 0.f) * g1);
            }
        } else {
            #pragma unroll
            for (int nt = 0; nt < NT; ++nt) {
                const int n = n0 + wn0 + nt * 8 + u0;
                const float c0 = biasArg[n], c1 = biasArg[n + 1];
                float2 o0 = make_float2(acc[mt][nt][0] + c0, acc[mt][nt][1] + c1);
                float2 o1 = make_float2(acc[mt][nt][2] + c0, acc[mt][nt][3] + c1);
                *(float2*)&OutArg[(size_t)r0 * DDATA + n]       = o0;
                *(float2*)&OutArg[(size_t)(r0 + 8) * DDATA + n] = o1;
            }
        }
    }
}

// ---------------------------------------------------------------------------
extern "C" void kernel_launch(void* const* d_in, const int* in_sizes, int n_in,
                              void* d_out, int out_size) {
    const float* x      = (const float*)d_in[0];
    const float* W_enc0 = (const float*)d_in[1];
    const float* b_enc0 = (const float*)d_in[2];
    const float* W_dec0 = (const float*)d_in[3];
    const float* b_dec0 = (const float*)d_in[4];
    const float* W_enc1 = (const float*)d_in[5];
    const float* b_enc1 = (const float*)d_in[6];
    const float* W_dec1 = (const float*)d_in[7];
    const float* b_dec1 = (const float*)d_in[8];
    float* out = (float*)d_out;

    k_round_x<<<B_ * DDATA / 256, 256>>>(x);
    k_t1<<<dim3(NSAE, DDATA / 32), dim3(32, 8)>>>(W_enc1);
    k_t2<<<dim3(KCAT / 32, DDATA / 32), dim3(32, 8)>>>(W_dec1, W_dec0, b_dec1);
    k_cb1<<<NSAE, 256>>>(W_enc1, b_enc1, b_dec1);
    k_acts0<<<B_ / 8, 128>>>(x, W_enc0, b_enc0, b_dec0);

    k_mma_gemm<64, DDATA, true>
        <<<dim3(NFLAT / 64, B_ / 128), 256>>>(nullptr, nullptr);
    k_mma_gemm<96, KCAT, false>
        <<<dim3(DDATA / 96, B_ / 128), 256>>>(b_dec0, out);
}

// round 12
// speedup vs baseline: 2.5640x; 1.0317x over previous
#include <cuda_runtime.h>
#include <cstdint>

// Problem constants
#define B_     2048
#define DDATA  768
#define DD0    128
#define NSAE   128
#define DD     32
#define NFLAT  4096
#define KCAT   4352   // NFLAT + 128 (acts0) + 128 (gate)

// Scratch. All k-dimensions stored with within-8-group column order
// [0,4,1,5,2,6,3,7] so mma fragment register pairs (k, k+4) are adjacent.
// Referenced ONLY from device code (host-side symbol decay = garbage ptrs).
__device__ float g_A1 [B_ * KCAT];      // (acts1 | acts0 | gate), k-permuted cols
__device__ float g_cb1[NFLAT];          // fused encoder bias, LOGICAL index
__device__ float g_xr [B_ * DDATA];     // x, tf32-rounded, d-permuted
__device__ float g_B1T[NFLAT * DDATA];  // [n][d] = W_enc1[n>>5][d][n&31], d-permuted
__device__ float g_B2T[DDATA * KCAT];   // [c][k] = Bcat[k][c], k-permuted

// ---------------------------------------------------------------------------
__device__ __forceinline__ int pos8(int u) {          // u in 0..7
    return (u < 4) ? (2 * u) : (2 * (u - 4) + 1);
}
__device__ __forceinline__ int g8pos(int u) {         // permute within 8-groups
    return (u & ~7) | pos8(u & 7);
}
__device__ __forceinline__ unsigned f2tf(float f) {
    unsigned u; asm("cvt.rna.tf32.f32 %0, %1;" : "=r"(u) : "f"(f)); return u;
}
__device__ __forceinline__ float tfr(float f) { return __uint_as_float(f2tf(f)); }

__device__ __forceinline__ void cp16(void* smemp, const void* g) {
    unsigned s = (unsigned)__cvta_generic_to_shared(smemp);
    asm volatile("cp.async.cg.shared.global [%0], [%1], 16;\n" :: "r"(s), "l"(g));
}
__device__ __forceinline__ void cp_commit() { asm volatile("cp.async.commit_group;\n"); }
template<int N> __device__ __forceinline__ void cp_wait() {
    asm volatile("cp.async.wait_group %0;\n" :: "n"(N));
}
__device__ __forceinline__ void mma_tf32(float* d, const uint32_t* a, const uint32_t* b) {
    asm volatile(
        "mma.sync.aligned.m16n8k8.row.col.f32.tf32.tf32.f32 "
        "{%0,%1,%2,%3}, {%4,%5,%6,%7}, {%8,%9}, {%0,%1,%2,%3};\n"
        : "+f"(d[0]), "+f"(d[1]), "+f"(d[2]), "+f"(d[3])
        : "r"(a[0]), "r"(a[1]), "r"(a[2]), "r"(a[3]), "r"(b[0]), "r"(b[1]));
}

// ---------------------------------------------------------------------------
// Prep kernels
// ---------------------------------------------------------------------------
// g_xr[b][perm(d)] = round(x[b][d])
__global__ void k_round_x(const float* __restrict__ x) {
    int i = blockIdx.x * blockDim.x + threadIdx.x;    // over B_*DDATA
    int row = i / DDATA, col = i % DDATA;
    g_xr[(size_t)row * DDATA + g8pos(col)] = tfr(x[i]);
}

// g_B1T[j*32+k][perm(d)] = round(W_enc1[j][d][k])
__global__ void k_t1(const float* __restrict__ W_enc1) {
    __shared__ float ts[32][33];
    const int j = blockIdx.x, d0 = blockIdx.y * 32;
    const int tx = threadIdx.x, ty = threadIdx.y;
    #pragma unroll
    for (int r = 0; r < 4; ++r) {
        int d = ty + 8 * r;
        ts[d][tx] = W_enc1[((size_t)j * DDATA + d0 + d) * DD + tx];
    }
    __syncthreads();
    #pragma unroll
    for (int r = 0; r < 4; ++r) {
        int k = ty + 8 * r;
        g_B1T[(size_t)(j * 32 + k) * DDATA + d0 + g8pos(tx)] = tfr(ts[tx][k]);
    }
}

// g_B2T[c][perm(kk)] = round(Bcat[kk][c]); Bcat = W_dec1 flat | W_dec0 | b_dec1
__global__ void k_t2(const float* __restrict__ W_dec1,
                     const float* __restrict__ W_dec0,
                     const float* __restrict__ b_dec1) {
    __shared__ float ts[32][33];
    const int kk0 = blockIdx.x * 32, c0 = blockIdx.y * 32;
    const int tx = threadIdx.x, ty = threadIdx.y;
    #pragma unroll
    for (int r = 0; r < 4; ++r) {
        int kr = kk0 + ty + 8 * r;
        const float* row = (kr < NFLAT) ? W_dec1 + (size_t)kr * DDATA
                         : (kr < NFLAT + 128) ? W_dec0 + (size_t)(kr - NFLAT) * DDATA
                         : b_dec1 + (size_t)(kr - NFLAT - 128) * DDATA;
        ts[ty + 8 * r][tx] = row[c0 + tx];
    }
    __syncthreads();
    #pragma unroll
    for (int r = 0; r < 4; ++r) {
        int c = ty + 8 * r;
        g_B2T[(size_t)(c0 + c) * KCAT + kk0 + g8pos(tx)] = tfr(ts[tx][c]);
    }
}

// cb1[n] = b_enc1[n] - sum_d b_dec1[n>>5][d] * W_enc1[n>>5][d][n&31]
// Warp-per-n, reading the already-transposed g_B1T coalescedly. Must run
// AFTER k_t1. (Uses tf32-rounded weights; b_dec1 == 0 in this problem so
// the value is exactly b_enc1 either way.)
__global__ void k_cb1(const float* __restrict__ b_enc1,
                      const float* __restrict__ b_dec1) {
    const int n = (blockIdx.x * blockDim.x + threadIdx.x) >> 5;  // 0..NFLAT-1
    const int lane = threadIdx.x & 31;
    const int j = n >> 5;
    const int sp = g8pos(lane);           // permuted offset within 32-group
    float s = 0.f;
    for (int i = 0; i < DDATA; i += 32)
        s += g_B1T[(size_t)n * DDATA + i + sp] * b_dec1[(size_t)j * DDATA + i + lane];
    #pragma unroll
    for (int o = 16; o; o >>= 1) s += __shfl_xor_sync(0xFFFFFFFFu, s, o);
    if (lane == 0) g_cb1[n] = b_enc1[n] - s;
}

// acts0 + gate, exact fp32 compute (gates must not be tf32-decided).
// Stored at permuted columns NFLAT + g8pos(j) and NFLAT + 128 + g8pos(j).
__global__ void k_acts0(const float* __restrict__ x,
                        const float* __restrict__ W_enc0,
                        const float* __restrict__ b_enc0,
                        const float* __restrict__ b_dec0) {
    __shared__ float xs[8 * DDATA];
    const int b0 = blockIdx.x * 8;
    const int j  = threadIdx.x;

    for (int idx = threadIdx.x; idx < 8 * DDATA; idx += 128)
        xs[idx] = x[(size_t)b0 * DDATA + idx] - b_dec0[idx % DDATA];
    __syncthreads();

    float acc[8];
    #pragma unroll
    for (int r = 0; r < 8; ++r) acc[r] = 0.f;
    for (int d = 0; d < DDATA; ++d) {
        float w = W_enc0[d * DD0 + j];
        #pragma unroll
        for (int r = 0; r < 8; ++r) acc[r] += xs[r * DDATA + d] * w;
    }
    float be = b_enc0[j];
    const int jp = g8pos(j);
    #pragma unroll
    for (int r = 0; r < 8; ++r) {
        float v = acc[r] + be;
        g_A1[(size_t)(b0 + r) * KCAT + NFLAT + jp]       = v > 0.f ? tfr(v) : 0.f;
        g_A1[(size_t)(b0 + r) * KCAT + NFLAT + 128 + jp] = v > 0.f ? 1.f : 0.f;
    }
}

// ---------------------------------------------------------------------------
// tf32 mma.sync GEMM, k-paired LDS.64 fragment loads, STATIC smem (<48KB).
// Buffers selected from DEVICE-SCOPE globals:
//   EPI1 (GEMM1, BN=128): A=g_xr, Bt=g_B1T, bias=g_cb1, Out=g_A1 (stride KCAT)
//   else (GEMM2, BN=96):  A=g_A1, Bt=g_B2T, bias=arg,   Out=arg (stride DDATA)
// 8 warps as 4(M) x 2(N); warp tile 32 x BN/2; KC=16 double-buffered cp.async.
// APAD may differ from BPAD to fit 48KB (APAD=20 has two benign 2-way
// conflict pairs; BPAD must be 24 for conflict-free B fragment LDS.64).
// ---------------------------------------------------------------------------
template<int BN, int KTOT, int APAD, int BPAD, bool EPI1>
__global__ __launch_bounds__(256, 2)
void k_mma_gemm(const float* __restrict__ biasArg, float* __restrict__ OutArg) {
    constexpr int BM = 128, KC = 16;
    constexpr int NT = BN / 16;                 // 8-wide n-frags per warp tile
    constexpr int T = KTOT / KC;

    const float* __restrict__ A  = EPI1 ? g_xr  : g_A1;
    const float* __restrict__ Bt = EPI1 ? g_B1T : g_B2T;

    __shared__ float Asm[2][BM][APAD];
    __shared__ float Bsm[2][BN][BPAD];

    const int tid = threadIdx.x, lane = tid & 31, wid = tid >> 5;
    const int wm0 = (wid & 3) * 32, wn0 = (wid >> 2) * (BN / 2);
    const int m0 = blockIdx.y * BM, n0 = blockIdx.x * BN;
    const int lr = lane >> 2, lc = lane & 3;

    auto loadChunk = [&](int st, int kt) {
        #pragma unroll
        for (int r = 0; r < 2; ++r) {
            int u = tid + 256 * r;               // 0..511: 128 rows x 4 cp16
            int row = u >> 2, c = u & 3;
            cp16(&Asm[st][row][c * 4],
                 A + (size_t)(m0 + row) * KTOT + kt + c * 4);
        }
        #pragma unroll
        for (int u = tid; u < BN * 4; u += 256) {
            int row = u >> 2, c = u & 3;
            cp16(&Bsm[st][row][c * 4],
                 Bt + (size_t)(n0 + row) * KTOT + kt + c * 4);
        }
        cp_commit();
    };

    float acc[2][NT][4] = {};

    loadChunk(0, 0);

    for (int t = 0; t < T; ++t) {
        const int st = t & 1;
        if (t + 1 < T) { loadChunk(st ^ 1, (t + 1) * KC); cp_wait<1>(); }
        else           { cp_wait<0>(); }
        __syncthreads();

        #pragma unroll
        for (int ks = 0; ks < 2; ++ks) {
            const int kb = ks * 8 + 2 * lc;      // stored pair = logical (lc, lc+4)
            uint32_t a[2][4];
            #pragma unroll
            for (int mt = 0; mt < 2; ++mt) {
                float2 lo = *(const float2*)&Asm[st][wm0 + mt * 16 + lr][kb];
                float2 hi = *(const float2*)&Asm[st][wm0 + mt * 16 + 8 + lr][kb];
                a[mt][0] = __float_as_uint(lo.x);   // a0: k=lc,   row m
                a[mt][1] = __float_as_uint(hi.x);   // a1: k=lc,   row m+8
                a[mt][2] = __float_as_uint(lo.y);   // a2: k=lc+4, row m
                a[mt][3] = __float_as_uint(hi.y);   // a3: k=lc+4, row m+8
            }
            #pragma unroll
            for (int nt = 0; nt < NT; ++nt) {
                float2 bv = *(const float2*)&Bsm[st][wn0 + nt * 8 + lr][kb];
                uint32_t b[2] = { __float_as_uint(bv.x), __float_as_uint(bv.y) };
                mma_tf32(acc[0][nt], a[0], b);
                mma_tf32(acc[1][nt], a[1], b);
            }
        }
        __syncthreads();
    }

    // Epilogue. D fragment cols (logical): u0 = 2*lc, u1 = 2*lc + 1 within 8-tile.
    const int u0 = 2 * lc, u1 = 2 * lc + 1;
    #pragma unroll
    for (int mt = 0; mt < 2; ++mt) {
        const int r0 = m0 + wm0 + mt * 16 + lr;
        if (EPI1) {
            // warp n-tile = BN/2 = 64 logical cols = experts j0, j0+1
            const int j0 = (n0 + wn0) >> 5;
            float g0[2], g1[2];
            #pragma unroll
            for (int e = 0; e < 2; ++e) {
                g0[e] = g_A1[(size_t)r0 * KCAT + NFLAT + 128 + g8pos(j0 + e)];
                g1[e] = g_A1[(size_t)(r0 + 8) * KCAT + NFLAT + 128 + g8pos(j0 + e)];
            }
            #pragma unroll
            for (int nt = 0; nt < NT; ++nt) {
                const int nb = n0 + wn0 + nt * 8;       // logical tile base
                const int e  = nt >> 2;                 // expert within warp tile
                const float c0 = g_cb1[nb + u0], c1 = g_cb1[nb + u1];
                const int s0 = nb + pos8(u0), s1 = nb + pos8(u1);  // stored cols
                g_A1[(size_t)r0 * KCAT + s0] =
                    tfr(fmaxf(acc[mt][nt][0] + c0, 0.f) * g0[e]);
                g_A1[(size_t)r0 * KCAT + s1] =
                    tfr(fmaxf(acc[mt][nt][1] + c1, 0.f) * g0[e]);
                g_A1[(size_t)(r0 + 8) * KCAT + s0] =
                    tfr(fmaxf(acc[mt][nt][2] + c0, 0.f) * g1[e]);
                g_A1[(size_t)(r0 + 8) * KCAT + s1] =
                    tfr(fmaxf(acc[mt][nt][3] + c1, 0.f) * g1[e]);
            }
        } else {
            #pragma unroll
            for (int nt = 0; nt < NT; ++nt) {
                const int n = n0 + wn0 + nt * 8 + u0;
                const float c0 = biasArg[n], c1 = biasArg[n + 1];
                float2 o0 = make_float2(acc[mt][nt][0] + c0, acc[mt][nt][1] + c1);
                float2 o1 = make_float2(acc[mt][nt][2] + c0, acc[mt][nt][3] + c1);
                *(float2*)&OutArg[(size_t)r0 * DDATA + n]       = o0;
                *(float2*)&OutArg[(size_t)(r0 + 8) * DDATA + n] = o1;
            }
        }
    }
}

// ---------------------------------------------------------------------------
extern "C" void kernel_launch(void* const* d_in, const int* in_sizes, int n_in,
                              void* d_out, int out_size) {
    const float* x      = (const float*)d_in[0];
    const float* W_enc0 = (const float*)d_in[1];
    const float* b_enc0 = (const float*)d_in[2];
    const float* W_dec0 = (const float*)d_in[3];
    const float* b_dec0 = (const float*)d_in[4];
    const float* W_enc1 = (const float*)d_in[5];
    const float* b_enc1 = (const float*)d_in[6];
    const float* W_dec1 = (const float*)d_in[7];
    const float* b_dec1 = (const float*)d_in[8];
    float* out = (float*)d_out;

    k_round_x<<<B_ * DDATA / 256, 256>>>(x);
    k_t1<<<dim3(NSAE, DDATA / 32), dim3(32, 8)>>>(W_enc1);
    k_t2<<<dim3(KCAT / 32, DDATA / 32), dim3(32, 8)>>>(W_dec1, W_dec0, b_dec1);
    k_cb1<<<NFLAT / 8, 256>>>(b_enc1, b_dec1);   // after k_t1 (reads g_B1T)
    k_acts0<<<B_ / 8, 128>>>(x, W_enc0, b_enc0, b_dec0);

    // GEMM1: BN=128, smem = 2*128*(20+24)*4 = 45056 B
    k_mma_gemm<128, DDATA, 20, 24, true>
        <<<dim3(NFLAT / 128, B_ / 128), 256>>>(nullptr, nullptr);
    // GEMM2: BN=96, smem = 2*(128*24 + 96*24)*4 = 43008 B, one clean wave
    k_mma_gemm<96, KCAT, 24, 24, false>
        <<<dim3(DDATA / 96, B_ / 128), 256>>>(b_dec0, out);
}

// round 14
// speedup vs baseline: 4.3993x; 1.7158x over previous
#include <cuda_runtime.h>
#include <cuda_fp16.h>
#include <cstdint>

// Problem constants
#define B_     2048
#define DDATA  768
#define DD0    128
#define NSAE   128
#define DD     32
#define NFLAT  4096
#define KCAT   4352   // NFLAT + 128 (acts0) + 128 (gate)

// Scratch (HALF). All k-dims stored with within-16-group order p16 =
// [0,1,8,9,2,3,10,11,4,5,12,13,6,7,14,15] so each thread's m16n8k16
// fragment halves (k = 2lc,2lc+1,2lc+8,2lc+9) are 4 contiguous = 1 LDS.64.
// Referenced ONLY from device code (host-side symbol decay = garbage ptrs).
__device__ __align__(16) __half g_A1 [B_ * KCAT];     // acts1|acts0|gate
__device__ __align__(16) __half g_xr [B_ * DDATA];    // x, d-permuted
__device__ __align__(16) __half g_B1T[NFLAT * DDATA]; // [n][d] enc weights
__device__ __align__(16) __half g_B2T[DDATA * KCAT];  // [c][k] dec cat
__device__ float g_cb1[NFLAT];                        // fused bias, LOGICAL idx

// ---------------------------------------------------------------------------
__device__ __forceinline__ int p16(int u) {           // u in 0..15, bijection
    return ((u >> 1) & 3) * 4 + (u >> 3) * 2 + (u & 1);
}
__device__ __forceinline__ int g16pos(int u) {        // permute within 16-groups
    return (u & ~15) | p16(u & 15);
}
__device__ __forceinline__ void cp16(void* smemp, const void* g) {
    unsigned s = (unsigned)__cvta_generic_to_shared(smemp);
    asm volatile("cp.async.cg.shared.global [%0], [%1], 16;\n" :: "r"(s), "l"(g));
}
__device__ __forceinline__ void cp_commit() { asm volatile("cp.async.commit_group;\n"); }
template<int N> __device__ __forceinline__ void cp_wait() {
    asm volatile("cp.async.wait_group %0;\n" :: "n"(N));
}
__device__ __forceinline__ void mma_f16(float* d, const uint32_t* a, const uint32_t* b) {
    asm volatile(
        "mma.sync.aligned.m16n8k16.row.col.f32.f16.f16.f32 "
        "{%0,%1,%2,%3}, {%4,%5,%6,%7}, {%8,%9}, {%0,%1,%2,%3};\n"
        : "+f"(d[0]), "+f"(d[1]), "+f"(d[2]), "+f"(d[3])
        : "r"(a[0]), "r"(a[1]), "r"(a[2]), "r"(a[3]), "r"(b[0]), "r"(b[1]));
}

// ---------------------------------------------------------------------------
// Prep kernels
// ---------------------------------------------------------------------------
// g_xr[b][perm(d)] = half(x[b][d])
__global__ void k_round_x(const float* __restrict__ x) {
    int i = blockIdx.x * blockDim.x + threadIdx.x;    // over B_*DDATA
    int row = i / DDATA, col = i % DDATA;
    g_xr[(size_t)row * DDATA + g16pos(col)] = __float2half_rn(x[i]);
}

// g_B1T[j*32+k][perm(d)] = half(W_enc1[j][d][k])
__global__ void k_t1(const float* __restrict__ W_enc1) {
    __shared__ float ts[32][33];
    const int j = blockIdx.x, d0 = blockIdx.y * 32;
    const int tx = threadIdx.x, ty = threadIdx.y;
    #pragma unroll
    for (int r = 0; r < 4; ++r) {
        int d = ty + 8 * r;
        ts[d][tx] = W_enc1[((size_t)j * DDATA + d0 + d) * DD + tx];
    }
    __syncthreads();
    #pragma unroll
    for (int r = 0; r < 4; ++r) {
        int k = ty + 8 * r;
        g_B1T[(size_t)(j * 32 + k) * DDATA + d0 + g16pos(tx)] = __float2half_rn(ts[tx][k]);
    }
}

// g_B2T[c][perm(kk)] = half(Bcat[kk][c]); Bcat = W_dec1 flat | W_dec0 | b_dec1
__global__ void k_t2(const float* __restrict__ W_dec1,
                     const float* __restrict__ W_dec0,
                     const float* __restrict__ b_dec1) {
    __shared__ float ts[32][33];
    const int kk0 = blockIdx.x * 32, c0 = blockIdx.y * 32;
    const int tx = threadIdx.x, ty = threadIdx.y;
    #pragma unroll
    for (int r = 0; r < 4; ++r) {
        int kr = kk0 + ty + 8 * r;
        const float* row = (kr < NFLAT) ? W_dec1 + (size_t)kr * DDATA
                         : (kr < NFLAT + 128) ? W_dec0 + (size_t)(kr - NFLAT) * DDATA
                         : b_dec1 + (size_t)(kr - NFLAT - 128) * DDATA;
        ts[ty + 8 * r][tx] = row[c0 + tx];
    }
    __syncthreads();
    #pragma unroll
    for (int r = 0; r < 4; ++r) {
        int c = ty + 8 * r;
        g_B2T[(size_t)(c0 + c) * KCAT + kk0 + g16pos(tx)] = __float2half_rn(ts[tx][c]);
    }
}

// cb1[n] = b_enc1[n] - sum_d b_dec1[n>>5][d]*W[n][d]  (b_dec1==0 here, exact)
// Warp-per-n over transposed g_B1T. Must run AFTER k_t1.
__global__ void k_cb1(const float* __restrict__ b_enc1,
                      const float* __restrict__ b_dec1) {
    const int n = (blockIdx.x * blockDim.x + threadIdx.x) >> 5;  // 0..NFLAT-1
    const int lane = threadIdx.x & 31;
    const int j = n >> 5;
    const int sp = g16pos(lane);          // permuted offset within 32-group
    float s = 0.f;
    for (int i = 0; i < DDATA; i += 32)
        s += __half2float(g_B1T[(size_t)n * DDATA + i + sp])
           * b_dec1[(size_t)j * DDATA + i + lane];
    #pragma unroll
    for (int o = 16; o; o >>= 1) s += __shfl_xor_sync(0xFFFFFFFFu, s, o);
    if (lane == 0) g_cb1[n] = b_enc1[n] - s;
}

// acts0 + gate, exact fp32 compute (gates must not be reduced-precision).
// Stored at permuted cols NFLAT + g16pos(j), NFLAT + 128 + g16pos(j).
__global__ void k_acts0(const float* __restrict__ x,
                        const float* __restrict__ W_enc0,
                        const float* __restrict__ b_enc0,
                        const float* __restrict__ b_dec0) {
    __shared__ float xs[8 * DDATA];
    const int b0 = blockIdx.x * 8;
    const int j  = threadIdx.x;

    for (int idx = threadIdx.x; idx < 8 * DDATA; idx += 128)
        xs[idx] = x[(size_t)b0 * DDATA + idx] - b_dec0[idx % DDATA];
    __syncthreads();

    float acc[8];
    #pragma unroll
    for (int r = 0; r < 8; ++r) acc[r] = 0.f;
    for (int d = 0; d < DDATA; ++d) {
        float w = W_enc0[d * DD0 + j];
        #pragma unroll
        for (int r = 0; r < 8; ++r) acc[r] += xs[r * DDATA + d] * w;
    }
    float be = b_enc0[j];
    const int jp = g16pos(j);
    #pragma unroll
    for (int r = 0; r < 8; ++r) {
        float v = acc[r] + be;
        g_A1[(size_t)(b0 + r) * KCAT + NFLAT + jp] =
            __float2half_rn(v > 0.f ? v : 0.f);
        g_A1[(size_t)(b0 + r) * KCAT + NFLAT + 128 + jp] =
            __float2half_rn(v > 0.f ? 1.f : 0.f);
    }
}

// ---------------------------------------------------------------------------
// fp16 mma.sync m16n8k16 GEMM. Blocked smem [stage][kb][row][16 halves]:
// row = 8 words -> fragment LDS.64 and cp.async stores are conflict-free
// with NO padding. KC=32 (2 kb per stage), double-buffered.
// Buffers from DEVICE-SCOPE globals:
//   EPI1 (GEMM1, BN=128): A=g_xr, Bt=g_B1T, bias=g_cb1, Out=g_A1 (half, KCAT)
//   else (GEMM2, BN=96):  A=g_A1, Bt=g_B2T, bias=arg,   Out=arg (f32, DDATA)
// 8 warps as 4(M) x 2(N); warp tile 32 x BN/2.
// ---------------------------------------------------------------------------
template<int BN, int KTOT, bool EPI1>
__global__ __launch_bounds__(256, 2)
void k_mma_gemm(const float* __restrict__ biasArg, float* __restrict__ OutArg) {
    constexpr int BM = 128, KC = 32;
    constexpr int NT = BN / 16;                 // 8-wide n-frags per warp tile
    constexpr int T = KTOT / KC;

    const __half* __restrict__ A  = EPI1 ? g_xr  : g_A1;
    const __half* __restrict__ Bt = EPI1 ? g_B1T : g_B2T;

    __shared__ __align__(16) __half Asm[2][2][BM][16];  // 16 KB
    __shared__ __align__(16) __half Bsm[2][2][BN][16];  // BN=128: 16 KB

    const int tid = threadIdx.x, lane = tid & 31, wid = tid >> 5;
    const int wm0 = (wid & 3) * 32, wn0 = (wid >> 2) * (BN / 2);
    const int m0 = blockIdx.y * BM, n0 = blockIdx.x * BN;
    const int lr = lane >> 2, lc = lane & 3;

    auto loadChunk = [&](int st, int kt) {
        #pragma unroll
        for (int r = 0; r < 2; ++r) {                    // A: 4*BM = 512 cp16
            int u = tid + 256 * r;
            int kb = u >> 8, rem = u & 255, row = rem >> 1, h0 = (rem & 1) * 8;
            cp16(&Asm[st][kb][row][h0],
                 A + (size_t)(m0 + row) * KTOT + kt + kb * 16 + h0);
        }
        for (int u = tid; u < 4 * BN; u += 256) {        // B: 4*BN cp16
            int kb = u / (2 * BN), rem = u % (2 * BN), row = rem >> 1,
                h0 = (rem & 1) * 8;
            cp16(&Bsm[st][kb][row][h0],
                 Bt + (size_t)(n0 + row) * KTOT + kt + kb * 16 + h0);
        }
        cp_commit();
    };

    float acc[2][NT][4] = {};

    loadChunk(0, 0);

    for (int t = 0; t < T; ++t) {
        const int st = t & 1;
        if (t + 1 < T) { loadChunk(st ^ 1, (t + 1) * KC); cp_wait<1>(); }
        else           { cp_wait<0>(); }
        __syncthreads();

        #pragma unroll
        for (int ks = 0; ks < 2; ++ks) {                 // ks = kb, k=16 each
            uint32_t a[2][4];
            #pragma unroll
            for (int mt = 0; mt < 2; ++mt) {
                uint2 lo = *(const uint2*)&Asm[st][ks][wm0 + mt * 16 + lr][4 * lc];
                uint2 hi = *(const uint2*)&Asm[st][ks][wm0 + mt * 16 + 8 + lr][4 * lc];
                a[mt][0] = lo.x;    // (row m,   k 2lc,2lc+1)
                a[mt][1] = hi.x;    // (row m+8, k 2lc,2lc+1)
                a[mt][2] = lo.y;    // (row m,   k 2lc+8,2lc+9)
                a[mt][3] = hi.y;    // (row m+8, k 2lc+8,2lc+9)
            }
            #pragma unroll
            for (int nt = 0; nt < NT; ++nt) {
                uint2 bv = *(const uint2*)&Bsm[st][ks][wn0 + nt * 8 + lr][4 * lc];
                uint32_t b[2] = { bv.x, bv.y };
                mma_f16(acc[0][nt], a[0], b);
                mma_f16(acc[1][nt], a[1], b);
            }
        }
        __syncthreads();
    }

    // Epilogue. D frag cols (logical): 2lc, 2lc+1 within each 8-col tile.
    const int u0 = 2 * lc;
    #pragma unroll
    for (int mt = 0; mt < 2; ++mt) {
        const int r0 = m0 + wm0 + mt * 16 + lr;
        if (EPI1) {
            const int j0 = (n0 + wn0) >> 5;     // warp n-tile 64 = experts j0,j0+1
            float g0[2], g1[2];
            #pragma unroll
            for (int e = 0; e < 2; ++e) {
                g0[e] = __half2float(g_A1[(size_t)r0 * KCAT + NFLAT + 128 + g16pos(j0 + e)]);
                g1[e] = __half2float(g_A1[(size_t)(r0 + 8) * KCAT + NFLAT + 128 + g16pos(j0 + e)]);
            }
            #pragma unroll
            for (int nt = 0; nt < NT; ++nt) {
                const int nb = n0 + wn0 + nt * 8;       // logical tile base
                const int e  = nt >> 2;                 // expert within warp tile
                const float c0 = g_cb1[nb + u0], c1 = g_cb1[nb + u0 + 1];
                // stored position: pair is adjacent under p16
                const int sc = (nb & ~15) + 4 * lc + 2 * (nt & 1);
                __half2 o0 = __floats2half2_rn(
                    fmaxf(acc[mt][nt][0] + c0, 0.f) * g0[e],
                    fmaxf(acc[mt][nt][1] + c1, 0.f) * g0[e]);
                __half2 o1 = __floats2half2_rn(
                    fmaxf(acc[mt][nt][2] + c0, 0.f) * g1[e],
                    fmaxf(acc[mt][nt][3] + c1, 0.f) * g1[e]);
                *(__half2*)&g_A1[(size_t)r0 * KCAT + sc]       = o0;
                *(__half2*)&g_A1[(size_t)(r0 + 8) * KCAT + sc] = o1;
            }
        } else {
            #pragma unroll
            for (int nt = 0; nt < NT; ++nt) {
                const int n = n0 + wn0 + nt * 8 + u0;
                const float c0 = biasArg[n], c1 = biasArg[n + 1];
                float2 o0 = make_float2(acc[mt][nt][0] + c0, acc[mt][nt][1] + c1);
                float2 o1 = make_float2(acc[mt][nt][2] + c0, acc[mt][nt][3] + c1);
                *(float2*)&OutArg[(size_t)r0 * DDATA + n]       = o0;
                *(float2*)&OutArg[(size_t)(r0 + 8) * DDATA + n] = o1;
            }
        }
    }
}

// ---------------------------------------------------------------------------
extern "C" void kernel_launch(void* const* d_in, const int* in_sizes, int n_in,
                              void* d_out, int out_size) {
    const float* x      = (const float*)d_in[0];
    const float* W_enc0 = (const float*)d_in[1];
    const float* b_enc0 = (const float*)d_in[2];
    const float* W_dec0 = (const float*)d_in[3];
    const float* b_dec0 = (const float*)d_in[4];
    const float* W_enc1 = (const float*)d_in[5];
    const float* b_enc1 = (const float*)d_in[6];
    const float* W_dec1 = (const float*)d_in[7];
    const float* b_dec1 = (const float*)d_in[8];
    float* out = (float*)d_out;

    k_round_x<<<B_ * DDATA / 256, 256>>>(x);
    k_t1<<<dim3(NSAE, DDATA / 32), dim3(32, 8)>>>(W_enc1);
    k_t2<<<dim3(KCAT / 32, DDATA / 32), dim3(32, 8)>>>(W_dec1, W_dec0, b_dec1);
    k_cb1<<<NFLAT / 8, 256>>>(b_enc1, b_dec1);   // after k_t1 (reads g_B1T)
    k_acts0<<<B_ / 8, 128>>>(x, W_enc0, b_enc0, b_dec0);

    // GEMM1: BN=128, smem 32 KB static
    k_mma_gemm<128, DDATA, true>
        <<<dim3(NFLAT / 128, B_ / 128), 256>>>(nullptr, nullptr);
    // GEMM2: BN=96, smem 28 KB static, 128 CTAs = one clean wave
    k_mma_gemm<96, KCAT, false>
        <<<dim3(DDATA / 96, B_ / 128), 256>>>(b_dec0, out);
}

// round 17
// speedup vs baseline: 4.7893x; 1.0886x over previous
#include <cuda_runtime.h>
#include <cuda_fp16.h>
#include <cstdint>

// Problem constants
#define B_     2048
#define DDATA  768
#define DD0    128
#define NSAE   128
#define DD     32
#define NFLAT  4096
#define KCAT   4352   // NFLAT + 128 (acts0) + 128 (gate)

// Scratch (HALF). All k-dims stored with within-32-group order p32 so each
// thread's m16n8k16 fragment halves for a FULL k=32 chunk (both k16 blocks)
// are 8 contiguous halves = one LDS.128.
// Referenced ONLY from device code (host-side symbol decay = garbage ptrs).
__device__ __align__(16) __half g_A1 [B_ * KCAT];     // acts1|acts0|gate
__device__ __align__(16) __half g_xr [B_ * DDATA];    // x, d-permuted
__device__ __align__(16) __half g_B1T[NFLAT * DDATA]; // [n][d] enc weights
__device__ __align__(16) __half g_B2T[DDATA * KCAT];  // [c][k] dec cat
__device__ float g_cb1[NFLAT];                        // fused bias, LOGICAL idx

// ---------------------------------------------------------------------------
__device__ __forceinline__ int p32(int u) {           // u in 0..31, bijection
    return ((u >> 1) & 3) * 8 + (u >> 4) * 4 + ((u >> 3) & 1) * 2 + (u & 1);
}
__device__ __forceinline__ int g32pos(int u) {        // permute within 32-groups
    return (u & ~31) | p32(u & 31);
}
__device__ __forceinline__ void cp16(void* smemp, const void* g) {
    unsigned s = (unsigned)__cvta_generic_to_shared(smemp);
    asm volatile("cp.async.cg.shared.global [%0], [%1], 16;\n" :: "r"(s), "l"(g));
}
__device__ __forceinline__ void cp_commit() { asm volatile("cp.async.commit_group;\n"); }
template<int N> __device__ __forceinline__ void cp_wait() {
    asm volatile("cp.async.wait_group %0;\n" :: "n"(N));
}
__device__ __forceinline__ void mma_f16(float* d, uint32_t a0, uint32_t a1,
                                        uint32_t a2, uint32_t a3,
                                        uint32_t b0, uint32_t b1) {
    asm volatile(
        "mma.sync.aligned.m16n8k16.row.col.f32.f16.f16.f32 "
        "{%0,%1,%2,%3}, {%4,%5,%6,%7}, {%8,%9}, {%0,%1,%2,%3};\n"
        : "+f"(d[0]), "+f"(d[1]), "+f"(d[2]), "+f"(d[3])
        : "r"(a0), "r"(a1), "r"(a2), "r"(a3), "r"(b0), "r"(b1));
}

// ---------------------------------------------------------------------------
// Prep kernels
// ---------------------------------------------------------------------------
// g_xr[b][perm(d)] = half(x[b][d])
__global__ void k_round_x(const float* __restrict__ x) {
    int i = blockIdx.x * blockDim.x + threadIdx.x;    // over B_*DDATA
    int row = i / DDATA, col = i % DDATA;
    g_xr[(size_t)row * DDATA + g32pos(col)] = __float2half_rn(x[i]);
}

// g_B1T[j*32+k][perm(d)] = half(W_enc1[j][d][k])
__global__ void k_t1(const float* __restrict__ W_enc1) {
    __shared__ float ts[32][33];
    const int j = blockIdx.x, d0 = blockIdx.y * 32;
    const int tx = threadIdx.x, ty = threadIdx.y;
    #pragma unroll
    for (int r = 0; r < 4; ++r) {
        int d = ty + 8 * r;
        ts[d][tx] = W_enc1[((size_t)j * DDATA + d0 + d) * DD + tx];
    }
    __syncthreads();
    #pragma unroll
    for (int r = 0; r < 4; ++r) {
        int k = ty + 8 * r;
        g_B1T[(size_t)(j * 32 + k) * DDATA + d0 + g32pos(tx)] = __float2half_rn(ts[tx][k]);
    }
}

// g_B2T[c][perm(kk)] = half(Bcat[kk][c]); Bcat = W_dec1 flat | W_dec0 | b_dec1
__global__ void k_t2(const float* __restrict__ W_dec1,
                     const float* __restrict__ W_dec0,
                     const float* __restrict__ b_dec1) {
    __shared__ float ts[32][33];
    const int kk0 = blockIdx.x * 32, c0 = blockIdx.y * 32;
    const int tx = threadIdx.x, ty = threadIdx.y;
    #pragma unroll
    for (int r = 0; r < 4; ++r) {
        int kr = kk0 + ty + 8 * r;
        const float* row = (kr < NFLAT) ? W_dec1 + (size_t)kr * DDATA
                         : (kr < NFLAT + 128) ? W_dec0 + (size_t)(kr - NFLAT) * DDATA
                         : b_dec1 + (size_t)(kr - NFLAT - 128) * DDATA;
        ts[ty + 8 * r][tx] = row[c0 + tx];
    }
    __syncthreads();
    #pragma unroll
    for (int r = 0; r < 4; ++r) {
        int c = ty + 8 * r;
        g_B2T[(size_t)(c0 + c) * KCAT + kk0 + g32pos(tx)] = __float2half_rn(ts[tx][c]);
    }
}

// cb1[n] = b_enc1[n] - sum_d b_dec1[n>>5][d]*W[n][d]  (b_dec1==0 here, exact)
// Warp-per-n over transposed g_B1T. Must run AFTER k_t1.
__global__ void k_cb1(const float* __restrict__ b_enc1,
                      const float* __restrict__ b_dec1) {
    const int n = (blockIdx.x * blockDim.x + threadIdx.x) >> 5;  // 0..NFLAT-1
    const int lane = threadIdx.x & 31;
    const int j = n >> 5;
    const int sp = g32pos(lane);          // permuted offset within 32-group
    float s = 0.f;
    for (int i = 0; i < DDATA; i += 32)
        s += __half2float(g_B1T[(size_t)n * DDATA + i + sp])
           * b_dec1[(size_t)j * DDATA + i + lane];
    #pragma unroll
    for (int o = 16; o; o >>= 1) s += __shfl_xor_sync(0xFFFFFFFFu, s, o);
    if (lane == 0) g_cb1[n] = b_enc1[n] - s;
}

// acts0 + gate, exact fp32 compute (gates must not be reduced-precision).
// Stored at permuted cols NFLAT + g32pos(j), NFLAT + 128 + g32pos(j).
__global__ void k_acts0(const float* __restrict__ x,
                        const float* __restrict__ W_enc0,
                        const float* __restrict__ b_enc0,
                        const float* __restrict__ b_dec0) {
    __shared__ float xs[8 * DDATA];
    const int b0 = blockIdx.x * 8;
    const int j  = threadIdx.x;

    for (int idx = threadIdx.x; idx < 8 * DDATA; idx += 128)
        xs[idx] = x[(size_t)b0 * DDATA + idx] - b_dec0[idx % DDATA];
    __syncthreads();

    float acc[8];
    #pragma unroll
    for (int r = 0; r < 8; ++r) acc[r] = 0.f;
    for (int d = 0; d < DDATA; ++d) {
        float w = W_enc0[d * DD0 + j];
        #pragma unroll
        for (int r = 0; r < 8; ++r) acc[r] += xs[r * DDATA + d] * w;
    }
    float be = b_enc0[j];
    const int jp = g32pos(j);
    #pragma unroll
    for (int r = 0; r < 8; ++r) {
        float v = acc[r] + be;
        g_A1[(size_t)(b0 + r) * KCAT + NFLAT + jp] =
            __float2half_rn(v > 0.f ? v : 0.f);
        g_A1[(size_t)(b0 + r) * KCAT + NFLAT + 128 + jp] =
            __float2half_rn(v > 0.f ? 1.f : 0.f);
    }
}

// ---------------------------------------------------------------------------
// fp16 mma.sync m16n8k16 GEMM. Smem [stage][row][32 halves] (64B rows):
// one LDS.128 per thread yields a thread's fragments for BOTH k16 blocks of
// a k=32 chunk; quarter-warp phases hit all 32 banks once (conflict-free,
// no padding). KC=32. NSTG=2: classic double buffer (2 syncs/iter).
// NSTG=3: 3-stage, load-after-sync, ONE sync/iter (for long-K GEMM2).
//   EPI1 (GEMM1, BN=128): A=g_xr, Bt=g_B1T, bias=g_cb1, Out=g_A1 (half, KCAT)
//   else (GEMM2, BN=96):  A=g_A1, Bt=g_B2T, bias=arg,   Out=arg (f32, DDATA)
// 8 warps as 4(M) x 2(N); warp tile 32 x BN/2.
// ---------------------------------------------------------------------------
template<int BN, int KTOT, int NSTG, bool EPI1>
__global__ __launch_bounds__(256, 2)
void k_mma_gemm(const float* __restrict__ biasArg, float* __restrict__ OutArg) {
    constexpr int BM = 128, KC = 32;
    constexpr int NT = BN / 16;                 // 8-wide n-frags per warp tile
    constexpr int T = KTOT / KC;

    const __half* __restrict__ A  = EPI1 ? g_xr  : g_A1;
    const __half* __restrict__ Bt = EPI1 ? g_B1T : g_B2T;

    __shared__ __align__(16) __half Asm[NSTG][BM][32];
    __shared__ __align__(16) __half Bsm[NSTG][BN][32];

    const int tid = threadIdx.x, lane = tid & 31, wid = tid >> 5;
    const int wm0 = (wid & 3) * 32, wn0 = (wid >> 2) * (BN / 2);
    const int m0 = blockIdx.y * BM, n0 = blockIdx.x * BN;
    const int lr = lane >> 2, lc = lane & 3;

    auto loadChunk = [&](int st, int kt) {
        #pragma unroll
        for (int r = 0; r < 2; ++r) {                    // A: 512 cp16
            int u = tid + 256 * r, row = u >> 2, sg = u & 3;
            cp16(&Asm[st][row][sg * 8],
                 A + (size_t)(m0 + row) * KTOT + kt + sg * 8);
        }
        for (int u = tid; u < BN * 4; u += 256) {        // B: BN*4 cp16
            int row = u >> 2, sg = u & 3;
            cp16(&Bsm[st][row][sg * 8],
                 Bt + (size_t)(n0 + row) * KTOT + kt + sg * 8);
        }
        cp_commit();
    };

    float acc[2][NT][4] = {};

    auto compute = [&](int st) {
        uint4 av[2][2];
        #pragma unroll
        for (int mt = 0; mt < 2; ++mt) {
            av[mt][0] = *(const uint4*)&Asm[st][wm0 + mt * 16 + lr][lc * 8];
            av[mt][1] = *(const uint4*)&Asm[st][wm0 + mt * 16 + 8 + lr][lc * 8];
        }
        #pragma unroll
        for (int nt = 0; nt < NT; ++nt) {
            uint4 bv = *(const uint4*)&Bsm[st][wn0 + nt * 8 + lr][lc * 8];
            #pragma unroll
            for (int mt = 0; mt < 2; ++mt) {
                mma_f16(acc[mt][nt], av[mt][0].x, av[mt][1].x,
                        av[mt][0].y, av[mt][1].y, bv.x, bv.y);   // k16 block 0
                mma_f16(acc[mt][nt], av[mt][0].z, av[mt][1].z,
                        av[mt][0].w, av[mt][1].w, bv.z, bv.w);   // k16 block 1
            }
        }
    };

    if constexpr (NSTG == 2) {
        loadChunk(0, 0);
        for (int t = 0; t < T; ++t) {
            const int st = t & 1;
            if (t + 1 < T) { loadChunk(st ^ 1, (t + 1) * KC); cp_wait<1>(); }
            else           { cp_wait<0>(); }
            __syncthreads();
            compute(st);
            __syncthreads();
        }
    } else {
        loadChunk(0, 0);
        loadChunk(1, KC);
        for (int t = 0; t < T; ++t) {
            const int st = t % 3;
            if (t + 1 < T) cp_wait<1>(); else cp_wait<0>();
            __syncthreads();                 // covers visibility AND WAR
            if (t + 2 < T) loadChunk((t + 2) % 3, (t + 2) * KC);
            compute(st);
        }
    }

    // Epilogue. D frag cols (logical): 2lc, 2lc+1 within each 8-col tile.
    const int u0 = 2 * lc;
    #pragma unroll
    for (int mt = 0; mt < 2; ++mt) {
        const int r0 = m0 + wm0 + mt * 16 + lr;
        if (EPI1) {
            const int j0 = (n0 + wn0) >> 5;     // warp n-tile 64 = experts j0,j0+1
            float g0[2], g1[2];
            #pragma unroll
            for (int e = 0; e < 2; ++e) {
                g0[e] = __half2float(g_A1[(size_t)r0 * KCAT + NFLAT + 128 + g32pos(j0 + e)]);
                g1[e] = __half2float(g_A1[(size_t)(r0 + 8) * KCAT + NFLAT + 128 + g32pos(j0 + e)]);
            }
            #pragma unroll
            for (int nt = 0; nt < NT; ++nt) {
                const int nb = n0 + wn0 + nt * 8;       // logical tile base
                const int e  = nt >> 2;                 // expert within warp tile
                const float c0 = g_cb1[nb + u0], c1 = g_cb1[nb + u0 + 1];
                // stored col under p32: pair (b=0,1) adjacent
                const int sc = (nb & ~31) + lc * 8 + ((nb & 24) >> 2);
                __half2 o0 = __floats2half2_rn(
                    fmaxf(acc[mt][nt][0] + c0, 0.f) * g0[e],
                    fmaxf(acc[mt][nt][1] + c1, 0.f) * g0[e]);
                __half2 o1 = __floats2half2_rn(
                    fmaxf(acc[mt][nt][2] + c0, 0.f) * g1[e],
                    fmaxf(acc[mt][nt][3] + c1, 0.f) * g1[e]);
                *(__half2*)&g_A1[(size_t)r0 * KCAT + sc]       = o0;
                *(__half2*)&g_A1[(size_t)(r0 + 8) * KCAT + sc] = o1;
            }
        } else {
            #pragma unroll
            for (int nt = 0; nt < NT; ++nt) {
                const int n = n0 + wn0 + nt * 8 + u0;
                const float c0 = biasArg[n], c1 = biasArg[n + 1];
                float2 o0 = make_float2(acc[mt][nt][0] + c0, acc[mt][nt][1] + c1);
                float2 o1 = make_float2(acc[mt][nt][2] + c0, acc[mt][nt][3] + c1);
                *(float2*)&OutArg[(size_t)r0 * DDATA + n]       = o0;
                *(float2*)&OutArg[(size_t)(r0 + 8) * DDATA + n] = o1;
            }
        }
    }
}

// ---------------------------------------------------------------------------
extern "C" void kernel_launch(void* const* d_in, const int* in_sizes, int n_in,
                              void* d_out, int out_size) {
    const float* x      = (const float*)d_in[0];
    const float* W_enc0 = (const float*)d_in[1];
    const float* b_enc0 = (const float*)d_in[2];
    const float* W_dec0 = (const float*)d_in[3];
    const float* b_dec0 = (const float*)d_in[4];
    const float* W_enc1 = (const float*)d_in[5];
    const float* b_enc1 = (const float*)d_in[6];
    const float* W_dec1 = (const float*)d_in[7];
    const float* b_dec1 = (const float*)d_in[8];
    float* out = (float*)d_out;

    k_round_x<<<B_ * DDATA / 256, 256>>>(x);
    k_t1<<<dim3(NSAE, DDATA / 32), dim3(32, 8)>>>(W_enc1);
    k_t2<<<dim3(KCAT / 32, DDATA / 32), dim3(32, 8)>>>(W_dec1, W_dec0, b_dec1);
    k_cb1<<<NFLAT / 8, 256>>>(b_enc1, b_dec1);   // after k_t1 (reads g_B1T)
    k_acts0<<<B_ / 8, 128>>>(x, W_enc0, b_enc0, b_dec0);

    // GEMM1: BN=128, 2-stage, smem 32 KB static
    k_mma_gemm<128, DDATA, 2, true>
        <<<dim3(NFLAT / 128, B_ / 128), 256>>>(nullptr, nullptr);
    // GEMM2: BN=96, 3-stage (1 sync/iter), smem 42 KB, 128 CTAs = one wave
    k_mma_gemm<96, KCAT, 3, false>
        <<<dim3(DDATA / 96, B_ / 128), 256>>>(b_dec0, out);
}